// round 13
// baseline (speedup 1.0000x reference)
#include <cuda_runtime.h>
#include <stdint.h>

#define MDIM  41
#define HALF  20
#define NPAIR 1261                 // (m,n) pairs with |m+n| <= 20
#define NTRIP (NPAIR * MDIM)       // 51701 triplets
#define BATCH 128
#define TPB   256
#define TPT   8                    // t per thread
#define TBLK  (TPB * TPT)          // 2048 t per block
#define MAXP  56                   // pairs spanned by a 2049-t window (<=53)
#define NCPLX (26470912LL)         // 128*2*2*51701 (real-parts buffer, floats)
#define NFLT  (52941824LL)         // full interleaved-complex float count

__device__ __forceinline__ int pair_base(int i) {
    return (i <= HALF) ? (i * (i + 41)) >> 1
                       : 651 + (((102 - i) * (i - 21)) >> 1);
}

__device__ __forceinline__ void decode_pair(int p, int& im, int& in_, int& imn) {
    int i;
    if (p < 651) {
        i = (int)((-41.0f + __fsqrt_rn(1681.0f + 8.0f * (float)p)) * 0.5f);
    } else {
        float q = (float)(p - 651);
        i = 21 + (int)((81.0f - __fsqrt_rn(6561.0f - 8.0f * q)) * 0.5f);
    }
    if (i < 0) i = 0;
    if (i > 40) i = 40;
    while (i < 40 && pair_base(i + 1) <= p) i++;
    while (i > 0 && pair_base(i) > p) i--;
    int m   = i - HALF;
    int off = p - pair_base(i);
    int nlo = (m > 0) ? -HALF : -HALF - m;
    int n   = nlo + off;
    im  = i;
    in_ = n + HALF;
    imn = m + n + HALF;
}

__device__ __forceinline__ float4 make_e1(const float4* sE, int p) {
    int im, in_, imn;
    decode_pair(p, im, in_, imn);
    float4 a = sE[im], c = sE[in_], d = sE[imn];
    float abx0 = a.x*c.x - a.y*c.y;
    float aby0 = a.x*c.y + a.y*c.x;
    float abx1 = a.z*c.z - a.w*c.w;
    float aby1 = a.z*c.w + a.w*c.z;
    return make_float4(abx0*d.x + aby0*d.y,   // e1x0
                       aby0*d.x - abx0*d.y,   // e1y0
                       abx1*d.z + aby1*d.w,   // e1x1
                       aby1*d.z - abx1*d.w);  // e1y1
}

__device__ __forceinline__ uint32_t smem_u32(const void* p) {
    return (uint32_t)__cvta_generic_to_shared(p);
}

// ---------------- MODE 1: real-parts-only layout (primary) ----------------
// out as float2: element (b*2+nm)*NTRIP + t = {feat1.re, feat2.re}
// Full blocks: mode0 DMA window [t_lo, t_lo+2048), mode1 DMA window
// [t_lo+1, t_lo+2049) -> both global addresses 16B-aligned.
// Tail block: STG for mode0 [t_lo, NTRIP), mode1 [t_lo+1, NTRIP) + t=0.
__global__ void __launch_bounds__(TPB)
sofeat_kernel(const float* __restrict__ Er,
              const float* __restrict__ Ei,
              float2* __restrict__ out2)
{
    __shared__ float4 sE[MDIM];         // (re0, im0, re1, im1)
    __shared__ float  sT1[MDIM];
    __shared__ float2 sT2[MDIM];
    __shared__ float4 sE1[MAXP];
    __shared__ __align__(16) float2 sOut[2][TBLK];   // 32 KB staging

    const int tid  = threadIdx.x;
    const int b    = blockIdx.y;
    const int t_lo = blockIdx.x * TBLK;
    const bool full = (t_lo + TBLK <= NTRIP);
    const int t_hi = full ? t_lo + TBLK : NTRIP;
    const int p_lo = t_lo / MDIM;
    // pair window must cover t up to t_hi (mode1 shift reaches t_lo+TBLK)
    const int p_hi = (full ? (t_lo + TBLK) : (t_hi - 1)) / MDIM;
    const int np   = p_hi - p_lo + 1;               // <= 53

    if (tid < MDIM) {
        const float2* er2 = reinterpret_cast<const float2*>(Er + (size_t)b * (MDIM * 2));
        const float2* ei2 = reinterpret_cast<const float2*>(Ei + (size_t)b * (MDIM * 2));
        float2 er = er2[tid];
        float2 ei = ei2[tid];
        sE[tid] = make_float4(er.x, ei.x, er.y, ei.y);
    }
    __syncthreads();

    if (tid < MDIM) {
        float4 e = sE[tid];
        float4 q = sE[40 - tid];
        sT1[tid] = e.x*e.x + e.y*e.y + e.z*e.z + e.w*e.w;
        float2 t2;
        t2.x = e.x*q.x - e.y*q.y + e.z*q.z - e.w*q.w;
        t2.y = e.x*q.y + e.y*q.x + e.z*q.w + e.w*q.z;
        sT2[tid] = t2;
    }
    if (tid < np && p_lo + tid < NPAIR)
        sE1[tid] = make_e1(sE, p_lo + tid);
    __syncthreads();

    const size_t base0 = (size_t)(b * 2 + 0) * NTRIP;
    const size_t base1 = (size_t)(b * 2 + 1) * NTRIP;

    const int t0 = t_lo + tid;
    const unsigned pp = (unsigned)t0 / MDIM;
    const int kk0 = t0 - (int)pp * MDIM;
    const int lp0 = (int)(pp - (unsigned)p_lo);

    if (full) {
        #pragma unroll
        for (int jj = 0; jj < TPT; jj++) {
            // mode-0 index for t = t0 + jj*256 (256 = 6*41 + 10)
            int kka = kk0 + 10 * jj;
            int lpa = lp0 + 6 * jj;
            if (kka >= 2 * MDIM)      { kka -= 2 * MDIM; lpa += 2; }
            else if (kka >= MDIM)     { kka -= MDIM;     lpa += 1; }
            // mode-1 index for t+1
            int kkb = kka + 1, lpb = lpa;
            if (kkb == MDIM) { kkb = 0; lpb += 1; }

            const float4 ea = sE1[lpa];
            const float  t1a = sT1[kka];
            const float2 t2a = sT2[kka];
            const float4 eb = sE1[lpb];
            const float  t1b = sT1[kkb];
            const float2 t2b = sT2[kkb];

            const int l = tid + jj * TPB;
            sOut[0][l] = make_float2(ea.x * t1a, ea.x*t2a.x + ea.y*t2a.y);
            sOut[1][l] = make_float2(eb.z * t1b, eb.z*t2b.x + eb.w*t2b.y);
        }
        __syncthreads();

        if (tid == 0) {
            asm volatile("fence.proxy.async.shared::cta;" ::: "memory");
            const uint32_t s0 = smem_u32(&sOut[0][0]);
            const uint32_t s1 = smem_u32(&sOut[1][0]);
            void* g0 = (void*)(out2 + base0 + t_lo);        // 16B-aligned
            void* g1 = (void*)(out2 + base1 + t_lo + 1);    // 16B-aligned (odd+even+1 even)
            const unsigned bytes = TBLK * 8;                // 16384
            asm volatile("cp.async.bulk.global.shared::cta.bulk_group [%0], [%1], %2;"
                         :: "l"(g0), "r"(s0), "r"(bytes) : "memory");
            asm volatile("cp.async.bulk.global.shared::cta.bulk_group [%0], [%1], %2;"
                         :: "l"(g1), "r"(s1), "r"(bytes) : "memory");
            asm volatile("cp.async.bulk.commit_group;" ::: "memory");
            asm volatile("cp.async.bulk.wait_group 0;" ::: "memory");
        }
    } else {
        // TAIL block (one per batch): guarded STG
        // mode-1 t=0 special element
        if (tid == 0) {
            float4 e1 = make_e1(sE, 0);          // p=0, k=0
            out2[base1] = make_float2(e1.z * sT1[0],
                                      e1.z*sT2[0].x + e1.w*sT2[0].y);
        }
        #pragma unroll
        for (int jj = 0; jj < TPT; jj++) {
            const int t = t0 + jj * TPB;
            if (t >= NTRIP) break;
            int kka = kk0 + 10 * jj;
            int lpa = lp0 + 6 * jj;
            if (kka >= 2 * MDIM)      { kka -= 2 * MDIM; lpa += 2; }
            else if (kka >= MDIM)     { kka -= MDIM;     lpa += 1; }

            const float4 ea = sE1[lpa];
            out2[base0 + t] = make_float2(ea.x * sT1[kka],
                                          ea.x*sT2[kka].x + ea.y*sT2[kka].y);
            // mode-1 at t+1 (this block owns mode1 [t_lo+1, NTRIP))
            if (t + 1 < NTRIP) {
                int kkb = kka + 1, lpb = lpa;
                if (kkb == MDIM) { kkb = 0; lpb += 1; }
                const float4 eb = sE1[lpb];
                out2[base1 + t + 1] = make_float2(eb.z * sT1[kkb],
                                                  eb.z*sT2[kkb].x + eb.w*sT2[kkb].y);
            }
        }
    }
}

// ---------------- MODE 0 fallback: interleaved complex ----------------
#define FTPT  4
#define FTBLK (TPB * FTPT)
#define FMAXP 28
__global__ void __launch_bounds__(TPB)
sofeat_full_kernel(const float* __restrict__ Er,
                   const float* __restrict__ Ei,
                   float* __restrict__ out,
                   size_t cap_f)
{
    __shared__ float4 sE[MDIM];
    __shared__ float  sT1[MDIM];
    __shared__ float2 sT2[MDIM];
    __shared__ float4 sE1[FMAXP];

    const int tid  = threadIdx.x;
    const int b    = blockIdx.y;
    const int t_lo = blockIdx.x * FTBLK;
    const int t_hi = (t_lo + FTBLK < NTRIP) ? t_lo + FTBLK : NTRIP;
    const int p_lo = t_lo / MDIM;
    const int np   = (t_hi - 1) / MDIM - p_lo + 1;

    if (tid < MDIM) {
        const float2* er2 = reinterpret_cast<const float2*>(Er + (size_t)b * (MDIM * 2));
        const float2* ei2 = reinterpret_cast<const float2*>(Ei + (size_t)b * (MDIM * 2));
        float2 er = er2[tid];
        float2 ei = ei2[tid];
        sE[tid] = make_float4(er.x, ei.x, er.y, ei.y);
    }
    __syncthreads();
    if (tid < MDIM) {
        float4 e = sE[tid];
        float4 q = sE[40 - tid];
        sT1[tid] = e.x*e.x + e.y*e.y + e.z*e.z + e.w*e.w;
        float2 t2;
        t2.x = e.x*q.x - e.y*q.y + e.z*q.z - e.w*q.w;
        t2.y = e.x*q.y + e.y*q.x + e.z*q.w + e.w*q.z;
        sT2[tid] = t2;
    }
    if (tid < np)
        sE1[tid] = make_e1(sE, p_lo + tid);
    __syncthreads();

    int t = t_lo + tid;
    #pragma unroll
    for (int jj = 0; jj < FTPT; jj++, t += TPB) {
        if (t >= t_hi) break;
        const unsigned p  = (unsigned)t / MDIM;
        const int      kk = t - (int)p * MDIM;
        const float4 e1 = sE1[p - (unsigned)p_lo];
        const float  t1 = sT1[kk];
        const float2 t2 = sT2[kk];
        float4 v0 = make_float4(e1.x * t1, e1.y * t1,
                                e1.x*t2.x + e1.y*t2.y, e1.x*t2.y - e1.y*t2.x);
        float4 v1 = make_float4(e1.z * t1, e1.w * t1,
                                e1.z*t2.x + e1.w*t2.y, e1.z*t2.y - e1.w*t2.x);
        size_t f0 = (size_t)(b * 2 + 0) * (4 * (size_t)NTRIP) + 4 * (size_t)t;
        size_t f1 = (size_t)(b * 2 + 1) * (4 * (size_t)NTRIP) + 4 * (size_t)t;
        if (f0 + 4 <= cap_f) {
            *reinterpret_cast<float2*>(out + f0)     = make_float2(v0.x, v0.y);
            *reinterpret_cast<float2*>(out + f0 + 2) = make_float2(v0.z, v0.w);
        }
        if (f1 + 4 <= cap_f) {
            *reinterpret_cast<float2*>(out + f1)     = make_float2(v1.x, v1.y);
            *reinterpret_cast<float2*>(out + f1 + 2) = make_float2(v1.z, v1.w);
        }
    }
}

extern "C" void kernel_launch(void* const* d_in, const int* in_sizes, int n_in,
                              void* d_out, int out_size)
{
    if (!d_in || !d_out || n_in < 2) return;
    const float* Er = (const float*)d_in[0];
    const float* Ei = (const float*)d_in[1];
    if (!Er || !Ei) return;
    (void)in_sizes;

    const long long os = (long long)out_size;

    if (os == NCPLX || os == NCPLX * 4) {
        dim3 grid((NTRIP + TBLK - 1) / TBLK, BATCH);   // 26 x 128
        sofeat_kernel<<<grid, TPB>>>(Er, Ei, (float2*)d_out);
    } else if (os == NFLT || os == NFLT * 4) {
        dim3 grid((NTRIP + FTBLK - 1) / FTBLK, BATCH);
        sofeat_full_kernel<<<grid, TPB>>>(Er, Ei, (float*)d_out, (size_t)NFLT);
    } else {
        size_t cap = (os > 0) ? (size_t)os : 0;
        if (cap > (size_t)NFLT) cap = (size_t)NFLT;
        dim3 grid((NTRIP + FTBLK - 1) / FTBLK, BATCH);
        sofeat_full_kernel<<<grid, TPB>>>(Er, Ei, (float*)d_out, cap);
    }
}

// round 14
// speedup vs baseline: 1.0031x; 1.0031x over previous
#include <cuda_runtime.h>
#include <stdint.h>

#define MDIM  41
#define HALF  20
#define NPAIR 1261                 // (m,n) pairs with |m+n| <= 20
#define NTRIP (NPAIR * MDIM)       // 51701 triplets
#define BATCH 128
#define TPB   256
#define TPT   8                    // t per thread
#define TBLK  (TPB * TPT)          // 2048 t per block
#define MAXP  56                   // pairs spanned by a 2048-t window (<=52)
#define NCPLX (26470912LL)         // 128*2*2*51701 (real-parts buffer, floats)
#define NFLT  (52941824LL)         // full interleaved-complex float count

__device__ __forceinline__ int pair_base(int i) {
    return (i <= HALF) ? (i * (i + 41)) >> 1
                       : 651 + (((102 - i) * (i - 21)) >> 1);
}

__device__ __forceinline__ void decode_pair(int p, int& im, int& in_, int& imn) {
    int i;
    if (p < 651) {
        i = (int)((-41.0f + __fsqrt_rn(1681.0f + 8.0f * (float)p)) * 0.5f);
    } else {
        float q = (float)(p - 651);
        i = 21 + (int)((81.0f - __fsqrt_rn(6561.0f - 8.0f * q)) * 0.5f);
    }
    if (i < 0) i = 0;
    if (i > 40) i = 40;
    while (i < 40 && pair_base(i + 1) <= p) i++;
    while (i > 0 && pair_base(i) > p) i--;
    int m   = i - HALF;
    int off = p - pair_base(i);
    int nlo = (m > 0) ? -HALF : -HALF - m;
    int n   = nlo + off;
    im  = i;
    in_ = n + HALF;
    imn = m + n + HALF;
}

__device__ __forceinline__ float4 make_e1(const float4* sE, int p) {
    int im, in_, imn;
    decode_pair(p, im, in_, imn);
    float4 a = sE[im], c = sE[in_], d = sE[imn];
    float abx0 = a.x*c.x - a.y*c.y;
    float aby0 = a.x*c.y + a.y*c.x;
    float abx1 = a.z*c.z - a.w*c.w;
    float aby1 = a.z*c.w + a.w*c.z;
    return make_float4(abx0*d.x + aby0*d.y,   // e1x0
                       aby0*d.x - abx0*d.y,   // e1y0
                       abx1*d.z + aby1*d.w,   // e1x1
                       aby1*d.z - abx1*d.w);  // e1y1
}

// ---------------- MODE 1: real-parts-only layout (primary) ----------------
// out as float2: element (b*2+nm)*NTRIP + t = {feat1.re, feat2.re}
__global__ void __launch_bounds__(TPB)
sofeat_kernel(const float* __restrict__ Er,
              const float* __restrict__ Ei,
              float2* __restrict__ out2)
{
    __shared__ float4 sE[MDIM];      // (re0, im0, re1, im1)
    __shared__ float  sT1[MDIM];
    __shared__ float2 sT2[MDIM];
    __shared__ float4 sE1[MAXP];     // (e1x0, e1y0, e1x1, e1y1)

    const int tid  = threadIdx.x;
    const int b    = blockIdx.y;
    const int t_lo = blockIdx.x * TBLK;
    const int t_hi = (t_lo + TBLK < NTRIP) ? t_lo + TBLK : NTRIP;
    const int p_lo = t_lo / MDIM;
    const int np   = (t_hi - 1) / MDIM - p_lo + 1;   // <= 52

    // phase 0a: vector-load E[b] into shared
    if (tid < MDIM) {
        const float2* er2 = reinterpret_cast<const float2*>(Er + (size_t)b * (MDIM * 2));
        const float2* ei2 = reinterpret_cast<const float2*>(Ei + (size_t)b * (MDIM * 2));
        float2 er = er2[tid];
        float2 ei = ei2[tid];
        sE[tid] = make_float4(er.x, ei.x, er.y, ei.y);
    }
    __syncthreads();

    // phase 0b: terms; phase 1: E1 per pair
    if (tid < MDIM) {
        float4 e = sE[tid];
        float4 q = sE[40 - tid];
        sT1[tid] = e.x*e.x + e.y*e.y + e.z*e.z + e.w*e.w;
        float2 t2;
        t2.x = e.x*q.x - e.y*q.y + e.z*q.z - e.w*q.w;
        t2.y = e.x*q.y + e.y*q.x + e.z*q.w + e.w*q.z;
        sT2[tid] = t2;
    }
    if (tid < np)
        sE1[tid] = make_e1(sE, p_lo + tid);
    __syncthreads();

    const size_t base0 = (size_t)(b * 2 + 0) * NTRIP;
    const size_t base1 = (size_t)(b * 2 + 1) * NTRIP;

    const int t0 = t_lo + tid;
    const unsigned pp = (unsigned)t0 / MDIM;      // one divide
    const int kk0 = t0 - (int)pp * MDIM;
    const int lp0 = (int)(pp - (unsigned)p_lo);

    if (t_lo + TBLK <= NTRIP) {
        // FULL block: guard-free, independent per-iteration addressing
        #pragma unroll
        for (int jj = 0; jj < TPT; jj++) {
            int kkj = kk0 + 10 * jj;             // 256 = 6*41 + 10
            int lpj = lp0 + 6 * jj;
            if (kkj >= 2 * MDIM)      { kkj -= 2 * MDIM; lpj += 2; }
            else if (kkj >= MDIM)     { kkj -= MDIM;     lpj += 1; }

            const float4 e1 = sE1[lpj];
            const float  t1 = sT1[kkj];
            const float2 t2 = sT2[kkj];

            const int t = t0 + jj * TPB;
            out2[base0 + t] = make_float2(e1.x * t1, e1.x*t2.x + e1.y*t2.y);
            out2[base1 + t] = make_float2(e1.z * t1, e1.z*t2.x + e1.w*t2.y);
        }
    } else {
        // TAIL block (one per batch): guarded
        #pragma unroll
        for (int jj = 0; jj < TPT; jj++) {
            const int t = t0 + jj * TPB;
            if (t >= NTRIP) break;
            int kkj = kk0 + 10 * jj;
            int lpj = lp0 + 6 * jj;
            if (kkj >= 2 * MDIM)      { kkj -= 2 * MDIM; lpj += 2; }
            else if (kkj >= MDIM)     { kkj -= MDIM;     lpj += 1; }

            const float4 e1 = sE1[lpj];
            const float  t1 = sT1[kkj];
            const float2 t2 = sT2[kkj];
            out2[base0 + t] = make_float2(e1.x * t1, e1.x*t2.x + e1.y*t2.y);
            out2[base1 + t] = make_float2(e1.z * t1, e1.z*t2.x + e1.w*t2.y);
        }
    }
}

// ---------------- MODE 0 fallback: interleaved complex ----------------
#define FTPT  4
#define FTBLK (TPB * FTPT)
#define FMAXP 28
__global__ void __launch_bounds__(TPB)
sofeat_full_kernel(const float* __restrict__ Er,
                   const float* __restrict__ Ei,
                   float* __restrict__ out,
                   size_t cap_f)
{
    __shared__ float4 sE[MDIM];
    __shared__ float  sT1[MDIM];
    __shared__ float2 sT2[MDIM];
    __shared__ float4 sE1[FMAXP];

    const int tid  = threadIdx.x;
    const int b    = blockIdx.y;
    const int t_lo = blockIdx.x * FTBLK;
    const int t_hi = (t_lo + FTBLK < NTRIP) ? t_lo + FTBLK : NTRIP;
    const int p_lo = t_lo / MDIM;
    const int np   = (t_hi - 1) / MDIM - p_lo + 1;

    if (tid < MDIM) {
        const float2* er2 = reinterpret_cast<const float2*>(Er + (size_t)b * (MDIM * 2));
        const float2* ei2 = reinterpret_cast<const float2*>(Ei + (size_t)b * (MDIM * 2));
        float2 er = er2[tid];
        float2 ei = ei2[tid];
        sE[tid] = make_float4(er.x, ei.x, er.y, ei.y);
    }
    __syncthreads();
    if (tid < MDIM) {
        float4 e = sE[tid];
        float4 q = sE[40 - tid];
        sT1[tid] = e.x*e.x + e.y*e.y + e.z*e.z + e.w*e.w;
        float2 t2;
        t2.x = e.x*q.x - e.y*q.y + e.z*q.z - e.w*q.w;
        t2.y = e.x*q.y + e.y*q.x + e.z*q.w + e.w*q.z;
        sT2[tid] = t2;
    }
    if (tid < np)
        sE1[tid] = make_e1(sE, p_lo + tid);
    __syncthreads();

    int t = t_lo + tid;
    #pragma unroll
    for (int jj = 0; jj < FTPT; jj++, t += TPB) {
        if (t >= t_hi) break;
        const unsigned p  = (unsigned)t / MDIM;
        const int      kk = t - (int)p * MDIM;
        const float4 e1 = sE1[p - (unsigned)p_lo];
        const float  t1 = sT1[kk];
        const float2 t2 = sT2[kk];
        float4 v0 = make_float4(e1.x * t1, e1.y * t1,
                                e1.x*t2.x + e1.y*t2.y, e1.x*t2.y - e1.y*t2.x);
        float4 v1 = make_float4(e1.z * t1, e1.w * t1,
                                e1.z*t2.x + e1.w*t2.y, e1.z*t2.y - e1.w*t2.x);
        size_t f0 = (size_t)(b * 2 + 0) * (4 * (size_t)NTRIP) + 4 * (size_t)t;
        size_t f1 = (size_t)(b * 2 + 1) * (4 * (size_t)NTRIP) + 4 * (size_t)t;
        if (f0 + 4 <= cap_f) {
            *reinterpret_cast<float2*>(out + f0)     = make_float2(v0.x, v0.y);
            *reinterpret_cast<float2*>(out + f0 + 2) = make_float2(v0.z, v0.w);
        }
        if (f1 + 4 <= cap_f) {
            *reinterpret_cast<float2*>(out + f1)     = make_float2(v1.x, v1.y);
            *reinterpret_cast<float2*>(out + f1 + 2) = make_float2(v1.z, v1.w);
        }
    }
}

extern "C" void kernel_launch(void* const* d_in, const int* in_sizes, int n_in,
                              void* d_out, int out_size)
{
    if (!d_in || !d_out || n_in < 2) return;
    const float* Er = (const float*)d_in[0];
    const float* Ei = (const float*)d_in[1];
    if (!Er || !Ei) return;
    (void)in_sizes;

    const long long os = (long long)out_size;

    if (os == NCPLX || os == NCPLX * 4) {
        dim3 grid((NTRIP + TBLK - 1) / TBLK, BATCH);   // 26 x 128
        sofeat_kernel<<<grid, TPB>>>(Er, Ei, (float2*)d_out);
    } else if (os == NFLT || os == NFLT * 4) {
        dim3 grid((NTRIP + FTBLK - 1) / FTBLK, BATCH);
        sofeat_full_kernel<<<grid, TPB>>>(Er, Ei, (float*)d_out, (size_t)NFLT);
    } else {
        size_t cap = (os > 0) ? (size_t)os : 0;
        if (cap > (size_t)NFLT) cap = (size_t)NFLT;
        dim3 grid((NTRIP + FTBLK - 1) / FTBLK, BATCH);
        sofeat_full_kernel<<<grid, TPB>>>(Er, Ei, (float*)d_out, cap);
    }
}

// round 15
// speedup vs baseline: 1.0218x; 1.0187x over previous
#include <cuda_runtime.h>
#include <stdint.h>

#define MDIM  41
#define HALF  20
#define NPAIR 1261                 // (m,n) pairs with |m+n| <= 20
#define NTRIP (NPAIR * MDIM)       // 51701 triplets
#define BATCH 128
#define TPB   256
#define TPT   16                   // t per thread
#define TBLK  (TPB * TPT)          // 4096 t per block
#define MAXP  104                  // pairs spanned by a 4096-t window (<=101)
#define NCPLX (26470912LL)         // 128*2*2*51701 (real-parts buffer, floats)
#define NFLT  (52941824LL)         // full interleaved-complex float count

__device__ __forceinline__ int pair_base(int i) {
    return (i <= HALF) ? (i * (i + 41)) >> 1
                       : 651 + (((102 - i) * (i - 21)) >> 1);
}

__device__ __forceinline__ void decode_pair(int p, int& im, int& in_, int& imn) {
    int i;
    if (p < 651) {
        i = (int)((-41.0f + __fsqrt_rn(1681.0f + 8.0f * (float)p)) * 0.5f);
    } else {
        float q = (float)(p - 651);
        i = 21 + (int)((81.0f - __fsqrt_rn(6561.0f - 8.0f * q)) * 0.5f);
    }
    if (i < 0) i = 0;
    if (i > 40) i = 40;
    while (i < 40 && pair_base(i + 1) <= p) i++;
    while (i > 0 && pair_base(i) > p) i--;
    int m   = i - HALF;
    int off = p - pair_base(i);
    int nlo = (m > 0) ? -HALF : -HALF - m;
    int n   = nlo + off;
    im  = i;
    in_ = n + HALF;
    imn = m + n + HALF;
}

__device__ __forceinline__ float4 make_e1(const float4* sE, int p) {
    int im, in_, imn;
    decode_pair(p, im, in_, imn);
    float4 a = sE[im], c = sE[in_], d = sE[imn];
    float abx0 = a.x*c.x - a.y*c.y;
    float aby0 = a.x*c.y + a.y*c.x;
    float abx1 = a.z*c.z - a.w*c.w;
    float aby1 = a.z*c.w + a.w*c.z;
    return make_float4(abx0*d.x + aby0*d.y,   // e1x0
                       aby0*d.x - abx0*d.y,   // e1y0
                       abx1*d.z + aby1*d.w,   // e1x1
                       aby1*d.z - abx1*d.w);  // e1y1
}

// ---------------- MODE 1: real-parts-only layout (primary) ----------------
// out as float2: element (b*2+nm)*NTRIP + t = {feat1.re, feat2.re}
__global__ void __launch_bounds__(TPB)
sofeat_kernel(const float* __restrict__ Er,
              const float* __restrict__ Ei,
              float2* __restrict__ out2)
{
    __shared__ float4 sE[MDIM];      // (re0, im0, re1, im1)
    __shared__ float  sT1[MDIM];
    __shared__ float2 sT2[MDIM];
    __shared__ float4 sE1[MAXP];     // (e1x0, e1y0, e1x1, e1y1)

    const int tid  = threadIdx.x;
    const int b    = blockIdx.y;
    const int t_lo = blockIdx.x * TBLK;
    const int t_hi = (t_lo + TBLK < NTRIP) ? t_lo + TBLK : NTRIP;
    const int p_lo = t_lo / MDIM;
    const int np   = (t_hi - 1) / MDIM - p_lo + 1;   // <= 101

    // phase 0a: vector-load E[b] into shared
    if (tid < MDIM) {
        const float2* er2 = reinterpret_cast<const float2*>(Er + (size_t)b * (MDIM * 2));
        const float2* ei2 = reinterpret_cast<const float2*>(Ei + (size_t)b * (MDIM * 2));
        float2 er = er2[tid];
        float2 ei = ei2[tid];
        sE[tid] = make_float4(er.x, ei.x, er.y, ei.y);
    }
    __syncthreads();

    // phase 0b: terms; phase 1: E1 per pair
    if (tid < MDIM) {
        float4 e = sE[tid];
        float4 q = sE[40 - tid];
        sT1[tid] = e.x*e.x + e.y*e.y + e.z*e.z + e.w*e.w;
        float2 t2;
        t2.x = e.x*q.x - e.y*q.y + e.z*q.z - e.w*q.w;
        t2.y = e.x*q.y + e.y*q.x + e.z*q.w + e.w*q.z;
        sT2[tid] = t2;
    }
    if (tid < np)
        sE1[tid] = make_e1(sE, p_lo + tid);
    __syncthreads();

    const size_t base0 = (size_t)(b * 2 + 0) * NTRIP;
    const size_t base1 = (size_t)(b * 2 + 1) * NTRIP;

    const int t0 = t_lo + tid;
    const unsigned pp = (unsigned)t0 / MDIM;      // one divide
    const int kk0 = t0 - (int)pp * MDIM;
    const int lp0 = (int)(pp - (unsigned)p_lo);

    if (t_lo + TBLK <= NTRIP) {
        // FULL block: guard-free, closed-form per-iteration addressing
        #pragma unroll
        for (int jj = 0; jj < TPT; jj++) {
            // jj*256 = jj*6*41 + jj*10 ; fold jj*10 (0..150) into (q, r<41)
            const int add  = 10 * jj;
            int kkj = kk0 + (add % MDIM);
            int lpj = lp0 + 6 * jj + (add / MDIM);
            if (kkj >= MDIM) { kkj -= MDIM; lpj += 1; }

            const float4 e1 = sE1[lpj];
            const float  t1 = sT1[kkj];
            const float2 t2 = sT2[kkj];

            const int t = t0 + jj * TPB;
            out2[base0 + t] = make_float2(e1.x * t1, e1.x*t2.x + e1.y*t2.y);
            out2[base1 + t] = make_float2(e1.z * t1, e1.z*t2.x + e1.w*t2.y);
        }
    } else {
        // TAIL block (one per batch): guarded
        #pragma unroll
        for (int jj = 0; jj < TPT; jj++) {
            const int t = t0 + jj * TPB;
            if (t >= NTRIP) break;
            const int add  = 10 * jj;
            int kkj = kk0 + (add % MDIM);
            int lpj = lp0 + 6 * jj + (add / MDIM);
            if (kkj >= MDIM) { kkj -= MDIM; lpj += 1; }

            const float4 e1 = sE1[lpj];
            const float  t1 = sT1[kkj];
            const float2 t2 = sT2[kkj];
            out2[base0 + t] = make_float2(e1.x * t1, e1.x*t2.x + e1.y*t2.y);
            out2[base1 + t] = make_float2(e1.z * t1, e1.z*t2.x + e1.w*t2.y);
        }
    }
}

// ---------------- MODE 0 fallback: interleaved complex ----------------
#define FTPT  4
#define FTBLK (TPB * FTPT)
#define FMAXP 28
__global__ void __launch_bounds__(TPB)
sofeat_full_kernel(const float* __restrict__ Er,
                   const float* __restrict__ Ei,
                   float* __restrict__ out,
                   size_t cap_f)
{
    __shared__ float4 sE[MDIM];
    __shared__ float  sT1[MDIM];
    __shared__ float2 sT2[MDIM];
    __shared__ float4 sE1[FMAXP];

    const int tid  = threadIdx.x;
    const int b    = blockIdx.y;
    const int t_lo = blockIdx.x * FTBLK;
    const int t_hi = (t_lo + FTBLK < NTRIP) ? t_lo + FTBLK : NTRIP;
    const int p_lo = t_lo / MDIM;
    const int np   = (t_hi - 1) / MDIM - p_lo + 1;

    if (tid < MDIM) {
        const float2* er2 = reinterpret_cast<const float2*>(Er + (size_t)b * (MDIM * 2));
        const float2* ei2 = reinterpret_cast<const float2*>(Ei + (size_t)b * (MDIM * 2));
        float2 er = er2[tid];
        float2 ei = ei2[tid];
        sE[tid] = make_float4(er.x, ei.x, er.y, ei.y);
    }
    __syncthreads();
    if (tid < MDIM) {
        float4 e = sE[tid];
        float4 q = sE[40 - tid];
        sT1[tid] = e.x*e.x + e.y*e.y + e.z*e.z + e.w*e.w;
        float2 t2;
        t2.x = e.x*q.x - e.y*q.y + e.z*q.z - e.w*q.w;
        t2.y = e.x*q.y + e.y*q.x + e.z*q.w + e.w*q.z;
        sT2[tid] = t2;
    }
    if (tid < np)
        sE1[tid] = make_e1(sE, p_lo + tid);
    __syncthreads();

    int t = t_lo + tid;
    #pragma unroll
    for (int jj = 0; jj < FTPT; jj++, t += TPB) {
        if (t >= t_hi) break;
        const unsigned p  = (unsigned)t / MDIM;
        const int      kk = t - (int)p * MDIM;
        const float4 e1 = sE1[p - (unsigned)p_lo];
        const float  t1 = sT1[kk];
        const float2 t2 = sT2[kk];
        float4 v0 = make_float4(e1.x * t1, e1.y * t1,
                                e1.x*t2.x + e1.y*t2.y, e1.x*t2.y - e1.y*t2.x);
        float4 v1 = make_float4(e1.z * t1, e1.w * t1,
                                e1.z*t2.x + e1.w*t2.y, e1.z*t2.y - e1.w*t2.x);
        size_t f0 = (size_t)(b * 2 + 0) * (4 * (size_t)NTRIP) + 4 * (size_t)t;
        size_t f1 = (size_t)(b * 2 + 1) * (4 * (size_t)NTRIP) + 4 * (size_t)t;
        if (f0 + 4 <= cap_f) {
            *reinterpret_cast<float2*>(out + f0)     = make_float2(v0.x, v0.y);
            *reinterpret_cast<float2*>(out + f0 + 2) = make_float2(v0.z, v0.w);
        }
        if (f1 + 4 <= cap_f) {
            *reinterpret_cast<float2*>(out + f1)     = make_float2(v1.x, v1.y);
            *reinterpret_cast<float2*>(out + f1 + 2) = make_float2(v1.z, v1.w);
        }
    }
}

extern "C" void kernel_launch(void* const* d_in, const int* in_sizes, int n_in,
                              void* d_out, int out_size)
{
    if (!d_in || !d_out || n_in < 2) return;
    const float* Er = (const float*)d_in[0];
    const float* Ei = (const float*)d_in[1];
    if (!Er || !Ei) return;
    (void)in_sizes;

    const long long os = (long long)out_size;

    if (os == NCPLX || os == NCPLX * 4) {
        dim3 grid((NTRIP + TBLK - 1) / TBLK, BATCH);   // 13 x 128
        sofeat_kernel<<<grid, TPB>>>(Er, Ei, (float2*)d_out);
    } else if (os == NFLT || os == NFLT * 4) {
        dim3 grid((NTRIP + FTBLK - 1) / FTBLK, BATCH);
        sofeat_full_kernel<<<grid, TPB>>>(Er, Ei, (float*)d_out, (size_t)NFLT);
    } else {
        size_t cap = (os > 0) ? (size_t)os : 0;
        if (cap > (size_t)NFLT) cap = (size_t)NFLT;
        dim3 grid((NTRIP + FTBLK - 1) / FTBLK, BATCH);
        sofeat_full_kernel<<<grid, TPB>>>(Er, Ei, (float*)d_out, cap);
    }
}